// round 1
// baseline (speedup 1.0000x reference)
#include <cuda_runtime.h>
#include <cstdint>

#define D   512
#define NB  512     // context rows (B)
#define NM  65536   // memory rows (M)
#define MT  128     // m-tile per block
#define BT  128     // b-tile per block
#define KC  16      // k-chunk

// Scratch (no cudaMalloc allowed)
__device__ float g_ctxn[NB * D];                // normalized context
__device__ float g_minv[NM];                    // 1/||memory[m]||
__device__ unsigned long long g_best[NB];       // packed (key<<32)|~m

// ---------------- f32x2 helpers (sm_100+ packed fp32) ----------------
__device__ __forceinline__ unsigned long long pack_ff(float a, float b) {
    unsigned long long r;
    asm("mov.b64 %0, {%1, %2};" : "=l"(r) : "f"(a), "f"(b));
    return r;
}
__device__ __forceinline__ void fma2(unsigned long long& d,
                                     unsigned long long a,
                                     unsigned long long b) {
    asm("fma.rn.f32x2 %0, %1, %2, %0;" : "+l"(d) : "l"(a), "l"(b));
}
__device__ __forceinline__ void unpack_ff(unsigned long long v, float& lo, float& hi) {
    asm("mov.b64 {%0, %1}, %2;" : "=f"(lo), "=f"(hi) : "l"(v));
}

// ---------------- init ----------------
__global__ void init_best_kernel() {
    g_best[threadIdx.x] = 0ULL;   // any real packed key beats 0
}

// ---------------- normalize context rows ----------------
__global__ void ctx_norm_kernel(const float* __restrict__ ctx) {
    const int b = blockIdx.x;
    const int t = threadIdx.x;            // 128 threads, 128 float4 per row
    const float4* row = (const float4*)(ctx + (size_t)b * D);
    float4 v = row[t];
    float ss = v.x * v.x + v.y * v.y + v.z * v.z + v.w * v.w;
    #pragma unroll
    for (int o = 16; o; o >>= 1) ss += __shfl_xor_sync(0xffffffffu, ss, o);
    __shared__ float ws[4];
    if ((t & 31) == 0) ws[t >> 5] = ss;
    __syncthreads();
    float tot = ws[0] + ws[1] + ws[2] + ws[3];
    float sc = rsqrtf(fmaxf(tot, 1e-12f));   // per-b scale: argmax-invariant
    float4 o4 = make_float4(v.x * sc, v.y * sc, v.z * sc, v.w * sc);
    ((float4*)(g_ctxn + (size_t)b * D))[t] = o4;
}

// ---------------- memory inverse norms (one warp per row) ----------------
__global__ void mem_norm_kernel(const float* __restrict__ mem) {
    const int warp = threadIdx.x >> 5;
    const int lane = threadIdx.x & 31;
    const int m = blockIdx.x * 8 + warp;
    const float4* row = (const float4*)(mem + (size_t)m * D);
    float ss = 0.f;
    #pragma unroll
    for (int i = 0; i < 4; i++) {
        float4 v = row[lane + 32 * i];
        ss += v.x * v.x + v.y * v.y + v.z * v.z + v.w * v.w;
    }
    #pragma unroll
    for (int o = 16; o; o >>= 1) ss += __shfl_xor_sync(0xffffffffu, ss, o);
    if (lane == 0) g_minv[m] = rsqrtf(fmaxf(ss, 1e-12f));
}

// ---------------- fused GEMM + argmax ----------------
// Block: 128 m-rows x 128 b-cols, K=512 in chunks of 16.
// Thread (tx,ty) in 16x16: thread tile 8x8 held as 8 x (4 f32x2) accumulators.
// Split-vector layout (rows/cols {i*4..+3, 64+i*4..+3}) to limit LDS conflicts.
__global__ __launch_bounds__(256)
void score_kernel(const float* __restrict__ mem) {
    __shared__ float tile[2][KC][128];     // 16 KB; reused as argmax scratch
    float (*As)[128] = tile[0];            // memory tile, k-major
    float (*Bs)[128] = tile[1];            // context tile, k-major

    const int tid = threadIdx.x;
    const int tx  = tid & 15;              // b dimension
    const int ty  = tid >> 4;              // m dimension
    const int b0  = blockIdx.x * BT;       // x fastest -> m-tile shared in L2
    const int m0  = blockIdx.y * MT;

    unsigned long long acc[8][4];
    #pragma unroll
    for (int i = 0; i < 8; i++)
        #pragma unroll
        for (int j = 0; j < 4; j++) acc[i][j] = 0ULL;

    for (int kc = 0; kc < D; kc += KC) {
        #pragma unroll
        for (int it = 0; it < 2; it++) {
            int f = tid + it * 256;
            int r = f >> 2;
            int c = (f & 3) << 2;
            float4 va = *(const float4*)(mem    + (size_t)(m0 + r) * D + (kc + c));
            As[c + 0][r] = va.x; As[c + 1][r] = va.y;
            As[c + 2][r] = va.z; As[c + 3][r] = va.w;
            float4 vb = *(const float4*)(g_ctxn + (size_t)(b0 + r) * D + (kc + c));
            Bs[c + 0][r] = vb.x; Bs[c + 1][r] = vb.y;
            Bs[c + 2][r] = vb.z; Bs[c + 3][r] = vb.w;
        }
        __syncthreads();
        #pragma unroll
        for (int kk = 0; kk < KC; kk++) {
            float4 a0 = *(const float4*)&As[kk][ty * 4];
            float4 a1 = *(const float4*)&As[kk][64 + ty * 4];
            ulonglong2 bv0 = *(const ulonglong2*)&Bs[kk][tx * 4];
            ulonglong2 bv1 = *(const ulonglong2*)&Bs[kk][64 + tx * 4];
            unsigned long long bp[4] = { bv0.x, bv0.y, bv1.x, bv1.y };
            float av[8] = { a0.x, a0.y, a0.z, a0.w, a1.x, a1.y, a1.z, a1.w };
            #pragma unroll
            for (int i = 0; i < 8; i++) {
                unsigned long long ap = pack_ff(av[i], av[i]);
                #pragma unroll
                for (int j = 0; j < 4; j++) fma2(acc[i][j], ap, bp[j]);
            }
        }
        __syncthreads();
    }

    // Epilogue: scale by 1/||mem||, per-b argmax, block reduce, atomic merge.
    float minv[8];
    #pragma unroll
    for (int i = 0; i < 8; i++) {
        int rl = (i < 4) ? (ty * 4 + i) : (64 + ty * 4 + (i - 4));
        minv[i] = g_minv[m0 + rl];
    }

    unsigned long long* red = (unsigned long long*)tile;  // 2048 entries
    #pragma unroll
    for (int j = 0; j < 8; j++) {
        const int jp = j >> 1, hi = j & 1;
        float bestv = -1e38f;
        int bestm = 0;
        #pragma unroll
        for (int i = 0; i < 8; i++) {
            float lo, hf;
            unpack_ff(acc[i][jp], lo, hf);
            float s = (hi ? hf : lo) * minv[i];
            int rl = (i < 4) ? (ty * 4 + i) : (64 + ty * 4 + (i - 4));
            if (s > bestv) { bestv = s; bestm = m0 + rl; }   // strict >: first (smallest m) wins
        }
        unsigned u = __float_as_uint(bestv);
        u = (u & 0x80000000u) ? ~u : (u | 0x80000000u);      // order-preserving key
        unsigned long long p = ((unsigned long long)u << 32) | (unsigned)(~bestm);
        int cl = (j < 4) ? (tx * 4 + j) : (64 + tx * 4 + (j - 4));
        red[cl * 16 + ty] = p;
    }
    __syncthreads();
    if (tid < 128) {
        unsigned long long best = red[tid * 16];
        #pragma unroll
        for (int t = 1; t < 16; t++) {
            unsigned long long v = red[tid * 16 + t];
            if (v > best) best = v;
        }
        atomicMax(&g_best[b0 + tid], best);
    }
}

// ---------------- gather winning rows ----------------
__global__ void gather_kernel(const float* __restrict__ mem, float* __restrict__ out) {
    const int b = blockIdx.x;
    const int t = threadIdx.x;   // 128
    unsigned idx = ~(unsigned)(g_best[b] & 0xffffffffull);
    const float4* src = (const float4*)(mem + (size_t)idx * D);
    ((float4*)(out + (size_t)b * D))[t] = src[t];
}

// ---------------- launch ----------------
extern "C" void kernel_launch(void* const* d_in, const int* in_sizes, int n_in,
                              void* d_out, int out_size) {
    const float* ctx = (const float*)d_in[0];
    const float* mem = (const float*)d_in[1];
    if (n_in >= 2 && in_sizes[0] > in_sizes[1]) {   // robustness vs input order
        const float* t = ctx; ctx = mem; mem = t;
    }
    float* out = (float*)d_out;

    init_best_kernel<<<1, NB>>>();
    ctx_norm_kernel<<<NB, 128>>>(ctx);
    mem_norm_kernel<<<NM / 8, 256>>>(mem);
    dim3 grid(NB / BT, NM / MT);                    // (4, 512): b fastest for L2 reuse
    score_kernel<<<grid, 256>>>(mem);
    gather_kernel<<<NB, 128>>>(mem, out);
}

// round 4
// speedup vs baseline: 4.0513x; 4.0513x over previous
#include <cuda_runtime.h>
#include <cuda_bf16.h>
#include <cstdint>

#define D      512
#define NB     512       // context rows (B)
#define NM     65536     // memory rows (M)
#define BM     128       // m rows per CTA tile
#define BN     128       // b cols per CTA tile
#define BK     32        // k per pipeline stage
#define NMBLK  (NM / BM) // 512 m-blocks
#define NKS    (D / BK)  // 16 k stages
#define LDA    40        // padded smem row stride (elems) -> conflict-free ldmatrix
#define STAGE_E (BM * LDA)            // elems per operand per stage (5120)
#define STAGE_B (STAGE_E * 2)         // bytes (10240)
#define MARGIN 0.0078125f             // 2^-7 >= 2x worst-case bf16 dot error

// ---------------- device scratch (no cudaMalloc allowed) ----------------
__device__ float          g_ctxn[NB * D];          // normalized ctx fp32 (exact rescore)
__device__ __nv_bfloat16  g_ctxb[NB * D];          // normalized ctx bf16
__device__ __nv_bfloat16  g_memb[(size_t)NM * D];  // normalized mem bf16 (64MB)
__device__ float          g_minv[NM];
__device__ float          g_blkmax[(size_t)NB * NMBLK];  // [b][mblk]
__device__ int            g_ncand;
__device__ int            g_cand[NB * NMBLK];
__device__ unsigned long long g_best[NB];

// ---------------- init ----------------
__global__ void init_kernel() {
    g_best[threadIdx.x] = 0ULL;
    if (threadIdx.x == 0) g_ncand = 0;
}

// ---------------- ctx: normalize -> fp32 + bf16 ----------------
__global__ void ctx_prep_kernel(const float* __restrict__ ctx) {
    const int b = blockIdx.x;
    const int t = threadIdx.x;                     // 128 threads, one float4 each
    float4 v = ((const float4*)(ctx + (size_t)b * D))[t];
    float ss = v.x * v.x + v.y * v.y + v.z * v.z + v.w * v.w;
    #pragma unroll
    for (int o = 16; o; o >>= 1) ss += __shfl_xor_sync(0xffffffffu, ss, o);
    __shared__ float ws[4];
    if ((t & 31) == 0) ws[t >> 5] = ss;
    __syncthreads();
    float sc = rsqrtf(fmaxf(ws[0] + ws[1] + ws[2] + ws[3], 1e-12f));
    float4 n4 = make_float4(v.x * sc, v.y * sc, v.z * sc, v.w * sc);
    ((float4*)(g_ctxn + (size_t)b * D))[t] = n4;
    __nv_bfloat162 p0 = __floats2bfloat162_rn(n4.x, n4.y);
    __nv_bfloat162 p1 = __floats2bfloat162_rn(n4.z, n4.w);
    uint2 u = make_uint2(*(uint32_t*)&p0, *(uint32_t*)&p1);
    *(uint2*)(g_ctxb + (size_t)b * D + 4 * t) = u;
}

// ---------------- mem: inv-norm + normalized bf16 ----------------
__global__ void mem_prep_kernel(const float* __restrict__ mem) {
    const int warp = threadIdx.x >> 5;
    const int lane = threadIdx.x & 31;
    const int m = blockIdx.x * 8 + warp;
    const float4* row = (const float4*)(mem + (size_t)m * D);
    float4 v[4];
    float ss = 0.f;
    #pragma unroll
    for (int i = 0; i < 4; i++) {
        v[i] = row[lane + 32 * i];
        ss += v[i].x * v[i].x + v[i].y * v[i].y + v[i].z * v[i].z + v[i].w * v[i].w;
    }
    #pragma unroll
    for (int o = 16; o; o >>= 1) ss += __shfl_xor_sync(0xffffffffu, ss, o);
    float inv = rsqrtf(fmaxf(ss, 1e-12f));
    if (lane == 0) g_minv[m] = inv;
    #pragma unroll
    for (int i = 0; i < 4; i++) {
        __nv_bfloat162 p0 = __floats2bfloat162_rn(v[i].x * inv, v[i].y * inv);
        __nv_bfloat162 p1 = __floats2bfloat162_rn(v[i].z * inv, v[i].w * inv);
        uint2 u = make_uint2(*(uint32_t*)&p0, *(uint32_t*)&p1);
        *(uint2*)(g_memb + (size_t)m * D + 4 * (lane + 32 * i)) = u;
    }
}

// ---------------- asm helpers ----------------
__device__ __forceinline__ uint32_t smem_u32(const void* p) {
    uint32_t a;
    asm("{ .reg .u64 t; cvta.to.shared.u64 t, %1; cvt.u32.u64 %0, t; }" : "=r"(a) : "l"(p));
    return a;
}
__device__ __forceinline__ void cpa16(uint32_t dst, const void* src) {
    asm volatile("cp.async.cg.shared.global [%0], [%1], 16;" :: "r"(dst), "l"(src));
}
__device__ __forceinline__ void cpa_commit() {
    asm volatile("cp.async.commit_group;");
}
__device__ __forceinline__ void cpa_wait2() {
    asm volatile("cp.async.wait_group 2;");
}
__device__ __forceinline__ void ldsm_x4(uint32_t& r0, uint32_t& r1, uint32_t& r2, uint32_t& r3,
                                        uint32_t addr) {
    asm volatile("ldmatrix.sync.aligned.m8n8.x4.shared.b16 {%0,%1,%2,%3}, [%4];"
                 : "=r"(r0), "=r"(r1), "=r"(r2), "=r"(r3) : "r"(addr));
}
__device__ __forceinline__ void hmma(float* c, const uint32_t* a, uint32_t b0, uint32_t b1) {
    asm volatile(
        "mma.sync.aligned.m16n8k16.row.col.f32.bf16.bf16.f32 "
        "{%0,%1,%2,%3}, {%4,%5,%6,%7}, {%8,%9}, {%0,%1,%2,%3};"
        : "+f"(c[0]), "+f"(c[1]), "+f"(c[2]), "+f"(c[3])
        : "r"(a[0]), "r"(a[1]), "r"(a[2]), "r"(a[3]), "r"(b0), "r"(b1));
}

// ---------------- phase 1: bf16 GEMM + per-(b, mblk) max ----------------
// CTA: 128 m x 128 b, 256 threads (8 warps, 4 m-warps x 2 n-warps).
// Warp tile 32(m) x 64(n): 2 m-frags x 8 n-frags of m16n8k16.
#define SMEM_RED (3 * STAGE_B * 2)             // after 3 stages of A+B
#define SMEM_TOT (SMEM_RED + 4 * BN * 4)       // + sred[4][128] floats

__global__ __launch_bounds__(256, 2) void score_gemm_kernel() {
    extern __shared__ char sm[];
    const uint32_t smb = smem_u32(sm);
    const int tid  = threadIdx.x;
    const int lane = tid & 31;
    const int wid  = tid >> 5;
    const int wm   = wid & 3;
    const int wn   = wid >> 2;
    const int b0   = blockIdx.x * BN;
    const int mblk = blockIdx.y;
    const int m0   = mblk * BM;

    // per-thread load slots: 2 A chunks + 2 B chunks of 16B
    const int r0c = tid >> 2, c0c = tid & 3;
    const int r1c = (tid + 256) >> 2, c1c = (tid + 256) & 3;

    auto load_stage = [&](int ks) {
        const int st = ks % 3;
        const uint32_t aB = smb + st * (2 * STAGE_B);
        const uint32_t bB = aB + STAGE_B;
        const __nv_bfloat16* gA = g_memb + (size_t)(m0) * D + ks * BK;
        const __nv_bfloat16* gB = g_ctxb + (size_t)(b0) * D + ks * BK;
        cpa16(aB + (r0c * LDA + c0c * 8) * 2, gA + (size_t)r0c * D + c0c * 8);
        cpa16(aB + (r1c * LDA + c1c * 8) * 2, gA + (size_t)r1c * D + c1c * 8);
        cpa16(bB + (r0c * LDA + c0c * 8) * 2, gB + (size_t)r0c * D + c0c * 8);
        cpa16(bB + (r1c * LDA + c1c * 8) * 2, gB + (size_t)r1c * D + c1c * 8);
    };

    load_stage(0); cpa_commit();
    load_stage(1); cpa_commit();
    load_stage(2); cpa_commit();

    float acc[2][8][4];
    #pragma unroll
    for (int mi = 0; mi < 2; mi++)
        #pragma unroll
        for (int ni = 0; ni < 8; ni++)
            #pragma unroll
            for (int q = 0; q < 4; q++) acc[mi][ni][q] = 0.f;

    // ldmatrix lane address components
    const int a_row = (lane & 7) + ((lane >> 3) & 1) * 8;   // + kh sel via col
    const int a_col = (lane >> 4) * 8;
    const int b_row = (lane & 7) + ((lane >> 4) << 3);
    const int b_col = ((lane >> 3) & 1) * 8;

    for (int ks = 0; ks < NKS; ks++) {
        cpa_wait2();
        __syncthreads();
        const int st = ks % 3;
        const uint32_t aB = smb + st * (2 * STAGE_B);
        const uint32_t bB = aB + STAGE_B;
        #pragma unroll
        for (int kh = 0; kh < 2; kh++) {
            uint32_t af[2][4];
            #pragma unroll
            for (int mi = 0; mi < 2; mi++) {
                uint32_t addr = aB + ((wm * 32 + mi * 16 + a_row) * LDA + kh * 16 + a_col) * 2;
                ldsm_x4(af[mi][0], af[mi][1], af[mi][2], af[mi][3], addr);
            }
            #pragma unroll
            for (int p = 0; p < 4; p++) {
                uint32_t bf[4];
                uint32_t addr = bB + ((wn * 64 + p * 16 + b_row) * LDA + kh * 16 + b_col) * 2;
                ldsm_x4(bf[0], bf[1], bf[2], bf[3], addr);
                #pragma unroll
                for (int mi = 0; mi < 2; mi++) {
                    hmma(acc[mi][2 * p + 0], af[mi], bf[0], bf[1]);
                    hmma(acc[mi][2 * p + 1], af[mi], bf[2], bf[3]);
                }
            }
        }
        __syncthreads();
        if (ks + 3 < NKS) load_stage(ks + 3);
        cpa_commit();
    }

    // Epilogue: per-column (b) max over this CTA's 128 m rows.
    float* sred = (float*)(sm + SMEM_RED);
    #pragma unroll
    for (int ni = 0; ni < 8; ni++) {
        #pragma unroll
        for (int c2 = 0; c2 < 2; c2++) {
            float v = fmaxf(fmaxf(acc[0][ni][c2], acc[0][ni][c2 + 2]),
                            fmaxf(acc[1][ni][c2], acc[1][ni][c2 + 2]));
            v = fmaxf(v, __shfl_xor_sync(0xffffffffu, v, 4));
            v = fmaxf(v, __shfl_xor_sync(0xffffffffu, v, 8));
            v = fmaxf(v, __shfl_xor_sync(0xffffffffu, v, 16));
            if (lane < 4)
                sred[wm * BN + wn * 64 + ni * 8 + lane * 2 + c2] = v;
        }
    }
    __syncthreads();
    if (tid < BN) {
        float v = sred[tid];
        #pragma unroll
        for (int w = 1; w < 4; w++) v = fmaxf(v, sred[w * BN + tid]);
        g_blkmax[(size_t)(b0 + tid) * NMBLK + mblk] = v;
    }
}

// ---------------- phase 2: per-b global max + candidate emission ----------------
__global__ void select_kernel() {
    const int wid = threadIdx.x >> 5;
    const int lane = threadIdx.x & 31;
    const int b = blockIdx.x * 8 + wid;
    const float* row = g_blkmax + (size_t)b * NMBLK;
    float gmax = -1e38f;
    #pragma unroll
    for (int i = 0; i < NMBLK / 32; i++) gmax = fmaxf(gmax, row[lane + 32 * i]);
    #pragma unroll
    for (int o = 16; o; o >>= 1) gmax = fmaxf(gmax, __shfl_xor_sync(0xffffffffu, gmax, o));
    const float thr = gmax - MARGIN;
    #pragma unroll
    for (int i = 0; i < NMBLK / 32; i++) {
        int mb = lane + 32 * i;
        if (row[mb] >= thr) {
            int p = atomicAdd(&g_ncand, 1);
            g_cand[p] = (b << 16) | mb;
        }
    }
}

// ---------------- phase 3: exact fp32 rescore of candidate blocks ----------------
__global__ __launch_bounds__(256) void rescore_kernel(const float* __restrict__ mem) {
    __shared__ float ctx_s[D];
    const int tid = threadIdx.x;
    const int wid = tid >> 5;
    const int lane = tid & 31;
    const int ncand = *(volatile int*)&g_ncand;

    for (int c = blockIdx.x; c < ncand; c += gridDim.x) {
        const int e = g_cand[c];
        const int b = e >> 16;
        const int m0 = (e & 0xffff) * BM;
        ctx_s[tid] = g_ctxn[(size_t)b * D + tid];
        ctx_s[tid + 256] = g_ctxn[(size_t)b * D + tid + 256];
        __syncthreads();
        const float4* ctx4 = (const float4*)ctx_s;

        unsigned long long wbest = 0ULL;
        for (int r = 0; r < 16; r++) {
            const int row = m0 + wid * 16 + r;
            const float4* mrow = (const float4*)(mem + (size_t)row * D);
            float s = 0.f;
            #pragma unroll
            for (int j = 0; j < 4; j++) {
                float4 mv = mrow[lane + 32 * j];
                float4 cv = ctx4[lane + 32 * j];
                s += mv.x * cv.x + mv.y * cv.y + mv.z * cv.z + mv.w * cv.w;
            }
            #pragma unroll
            for (int o = 16; o; o >>= 1) s += __shfl_xor_sync(0xffffffffu, s, o);
            float sc = s * g_minv[row];
            unsigned u = __float_as_uint(sc);
            u = (u & 0x80000000u) ? ~u : (u | 0x80000000u);
            unsigned long long key = ((unsigned long long)u << 32) | (unsigned)(~row);
            if (key > wbest) wbest = key;
        }
        if (lane == 0) atomicMax(&g_best[b], wbest);
        __syncthreads();
    }
}

// ---------------- gather winning rows ----------------
__global__ void gather_kernel(const float* __restrict__ mem, float* __restrict__ out) {
    const int b = blockIdx.x;
    const int t = threadIdx.x;   // 128
    unsigned idx = ~(unsigned)(g_best[b] & 0xffffffffull);
    ((float4*)(out + (size_t)b * D))[t] = ((const float4*)(mem + (size_t)idx * D))[t];
}

// ---------------- launch ----------------
extern "C" void kernel_launch(void* const* d_in, const int* in_sizes, int n_in,
                              void* d_out, int out_size) {
    const float* ctx = (const float*)d_in[0];
    const float* mem = (const float*)d_in[1];
    if (n_in >= 2 && in_sizes[0] > in_sizes[1]) {
        const float* t = ctx; ctx = mem; mem = t;
    }
    float* out = (float*)d_out;

    cudaFuncSetAttribute(score_gemm_kernel,
                         cudaFuncAttributeMaxDynamicSharedMemorySize, SMEM_TOT);

    init_kernel<<<1, NB>>>();
    ctx_prep_kernel<<<NB, 128>>>(ctx);
    mem_prep_kernel<<<NM / 8, 256>>>(mem);
    dim3 grid(NB / BN, NM / BM);   // (4, 512): b fastest -> mem tiles shared in L2
    score_gemm_kernel<<<grid, 256, SMEM_TOT>>>();
    select_kernel<<<NB / 8, 256>>>();
    rescore_kernel<<<1024, 256>>>(mem);
    gather_kernel<<<NB, 128>>>(mem, out);
}

// round 5
// speedup vs baseline: 4.3301x; 1.0688x over previous
#include <cuda_runtime.h>
#include <cuda_bf16.h>
#include <cstdint>

#define D      512
#define NB     512       // context rows (B)
#define NM     65536     // memory rows (M)
#define BM     128       // m rows per CTA tile
#define BN     128       // b cols per CTA tile
#define BK     32        // k per pipeline stage
#define NSUB   (NM / 32) // 2048 sub-blocks of 32 rows
#define NKS    (D / BK)  // 16 k stages
#define NSTAGE 4
#define LDA    40        // padded smem row stride (elems) -> conflict-free ldmatrix
#define STAGE_E (BM * LDA)            // elems per operand per stage (5120)
#define STAGE_B (STAGE_E * 2)         // bytes (10240)
#define MARGIN 0.0078125f             // 2^-7 >= 2x worst-case bf16 dot error

// ---------------- device scratch (no cudaMalloc allowed) ----------------
__device__ float          g_ctxn[NB * D];          // normalized ctx fp32 (exact rescore)
__device__ __nv_bfloat16  g_ctxb[NB * D];          // normalized ctx bf16
__device__ __nv_bfloat16  g_memb[(size_t)NM * D];  // normalized mem bf16 (64MB)
__device__ float          g_minv[NM];
__device__ float          g_submax[(size_t)NB * NSUB];  // [b][sub] 4MB
__device__ int            g_ncand;
__device__ int            g_cand[NB * 64];
__device__ unsigned long long g_best[NB];

// ---------------- ctx: normalize -> fp32 + bf16 (also zero-inits state) ----------------
__global__ void ctx_prep_kernel(const float* __restrict__ ctx) {
    const int b = blockIdx.x;
    const int t = threadIdx.x;                     // 128 threads, one float4 each
    if (t == 0) {
        g_best[b] = 0ULL;
        if (b == 0) g_ncand = 0;
    }
    float4 v = ((const float4*)(ctx + (size_t)b * D))[t];
    float ss = v.x * v.x + v.y * v.y + v.z * v.z + v.w * v.w;
    #pragma unroll
    for (int o = 16; o; o >>= 1) ss += __shfl_xor_sync(0xffffffffu, ss, o);
    __shared__ float ws[4];
    if ((t & 31) == 0) ws[t >> 5] = ss;
    __syncthreads();
    float sc = rsqrtf(fmaxf(ws[0] + ws[1] + ws[2] + ws[3], 1e-12f));
    float4 n4 = make_float4(v.x * sc, v.y * sc, v.z * sc, v.w * sc);
    ((float4*)(g_ctxn + (size_t)b * D))[t] = n4;
    __nv_bfloat162 p0 = __floats2bfloat162_rn(n4.x, n4.y);
    __nv_bfloat162 p1 = __floats2bfloat162_rn(n4.z, n4.w);
    uint2 u = make_uint2(*(uint32_t*)&p0, *(uint32_t*)&p1);
    *(uint2*)(g_ctxb + (size_t)b * D + 4 * t) = u;
}

// ---------------- mem: inv-norm + normalized bf16 ----------------
__global__ void mem_prep_kernel(const float* __restrict__ mem) {
    const int warp = threadIdx.x >> 5;
    const int lane = threadIdx.x & 31;
    const int m = blockIdx.x * 8 + warp;
    const float4* row = (const float4*)(mem + (size_t)m * D);
    float4 v[4];
    float ss = 0.f;
    #pragma unroll
    for (int i = 0; i < 4; i++) {
        v[i] = row[lane + 32 * i];
        ss += v[i].x * v[i].x + v[i].y * v[i].y + v[i].z * v[i].z + v[i].w * v[i].w;
    }
    #pragma unroll
    for (int o = 16; o; o >>= 1) ss += __shfl_xor_sync(0xffffffffu, ss, o);
    float inv = rsqrtf(fmaxf(ss, 1e-12f));
    if (lane == 0) g_minv[m] = inv;
    #pragma unroll
    for (int i = 0; i < 4; i++) {
        __nv_bfloat162 p0 = __floats2bfloat162_rn(v[i].x * inv, v[i].y * inv);
        __nv_bfloat162 p1 = __floats2bfloat162_rn(v[i].z * inv, v[i].w * inv);
        uint2 u = make_uint2(*(uint32_t*)&p0, *(uint32_t*)&p1);
        *(uint2*)(g_memb + (size_t)m * D + 4 * (lane + 32 * i)) = u;
    }
}

// ---------------- asm helpers ----------------
__device__ __forceinline__ uint32_t smem_u32(const void* p) {
    uint32_t a;
    asm("{ .reg .u64 t; cvta.to.shared.u64 t, %1; cvt.u32.u64 %0, t; }" : "=r"(a) : "l"(p));
    return a;
}
__device__ __forceinline__ void cpa16(uint32_t dst, const void* src) {
    asm volatile("cp.async.cg.shared.global [%0], [%1], 16;" :: "r"(dst), "l"(src));
}
__device__ __forceinline__ void cpa_commit() {
    asm volatile("cp.async.commit_group;");
}
__device__ __forceinline__ void cpa_wait2() {
    asm volatile("cp.async.wait_group 2;");
}
__device__ __forceinline__ void ldsm_x4(uint32_t& r0, uint32_t& r1, uint32_t& r2, uint32_t& r3,
                                        uint32_t addr) {
    asm volatile("ldmatrix.sync.aligned.m8n8.x4.shared.b16 {%0,%1,%2,%3}, [%4];"
                 : "=r"(r0), "=r"(r1), "=r"(r2), "=r"(r3) : "r"(addr));
}
__device__ __forceinline__ void hmma(float* c, const uint32_t* a, uint32_t b0, uint32_t b1) {
    asm volatile(
        "mma.sync.aligned.m16n8k16.row.col.f32.bf16.bf16.f32 "
        "{%0,%1,%2,%3}, {%4,%5,%6,%7}, {%8,%9}, {%0,%1,%2,%3};"
        : "+f"(c[0]), "+f"(c[1]), "+f"(c[2]), "+f"(c[3])
        : "r"(a[0]), "r"(a[1]), "r"(a[2]), "r"(a[3]), "r"(b0), "r"(b1));
}

// ---------------- phase 1: bf16 GEMM + per-(b, 32-row-sub) max ----------------
// CTA: 128 m x 128 b, 256 threads (8 warps: 4 m-warps (wm) x 2 n-warps (wn)).
// Warp tile 32(m) x 64(n): 2 m-frags x 8 n-frags of m16n8k16.
#define SMEM_RED (NSTAGE * 2 * STAGE_B)        // 81920: after 4 stages of A+B
#define SMEM_TOT (SMEM_RED + BN * 4 * 4)       // + sred2[128][4] floats

__global__ __launch_bounds__(256, 2) void score_gemm_kernel() {
    extern __shared__ char sm[];
    const uint32_t smb = smem_u32(sm);
    const int tid  = threadIdx.x;
    const int lane = tid & 31;
    const int wid  = tid >> 5;
    const int wm   = wid & 3;
    const int wn   = wid >> 2;
    const int b0   = blockIdx.x * BN;
    const int mblk = blockIdx.y;
    const int m0   = mblk * BM;

    // per-thread load slots: 2 A chunks + 2 B chunks of 16B
    const int r0c = tid >> 2, c0c = tid & 3;
    const int r1c = (tid + 256) >> 2, c1c = (tid + 256) & 3;

    auto load_stage = [&](int ks) {
        const int st = ks & (NSTAGE - 1);
        const uint32_t aB = smb + st * (2 * STAGE_B);
        const uint32_t bB = aB + STAGE_B;
        const __nv_bfloat16* gA = g_memb + (size_t)m0 * D + ks * BK;
        const __nv_bfloat16* gB = g_ctxb + (size_t)b0 * D + ks * BK;
        cpa16(aB + (r0c * LDA + c0c * 8) * 2, gA + (size_t)r0c * D + c0c * 8);
        cpa16(aB + (r1c * LDA + c1c * 8) * 2, gA + (size_t)r1c * D + c1c * 8);
        cpa16(bB + (r0c * LDA + c0c * 8) * 2, gB + (size_t)r0c * D + c0c * 8);
        cpa16(bB + (r1c * LDA + c1c * 8) * 2, gB + (size_t)r1c * D + c1c * 8);
    };

    load_stage(0); cpa_commit();
    load_stage(1); cpa_commit();
    load_stage(2); cpa_commit();

    float acc[2][8][4];
    #pragma unroll
    for (int mi = 0; mi < 2; mi++)
        #pragma unroll
        for (int ni = 0; ni < 8; ni++)
            #pragma unroll
            for (int q = 0; q < 4; q++) acc[mi][ni][q] = 0.f;

    // ldmatrix lane address components
    const int a_row = (lane & 7) + ((lane >> 3) & 1) * 8;
    const int a_col = (lane >> 4) * 8;
    const int b_row = (lane & 7) + ((lane >> 4) << 3);
    const int b_col = ((lane >> 3) & 1) * 8;

    for (int ks = 0; ks < NKS; ks++) {
        cpa_wait2();                   // stage ks resident
        __syncthreads();               // visible to all; stage (ks+3)&3 free
        if (ks + 3 < NKS) load_stage(ks + 3);
        cpa_commit();                  // unconditional: keeps group count aligned

        const int st = ks & (NSTAGE - 1);
        const uint32_t aB = smb + st * (2 * STAGE_B);
        const uint32_t bB = aB + STAGE_B;
        #pragma unroll
        for (int kh = 0; kh < 2; kh++) {
            // batch all 6 ldmatrix first, then 16 HMMA (latency overlap)
            uint32_t af[2][4];
            uint32_t bf[4][4];
            #pragma unroll
            for (int mi = 0; mi < 2; mi++) {
                uint32_t addr = aB + ((wm * 32 + mi * 16 + a_row) * LDA + kh * 16 + a_col) * 2;
                ldsm_x4(af[mi][0], af[mi][1], af[mi][2], af[mi][3], addr);
            }
            #pragma unroll
            for (int p = 0; p < 4; p++) {
                uint32_t addr = bB + ((wn * 64 + p * 16 + b_row) * LDA + kh * 16 + b_col) * 2;
                ldsm_x4(bf[p][0], bf[p][1], bf[p][2], bf[p][3], addr);
            }
            #pragma unroll
            for (int p = 0; p < 4; p++)
                #pragma unroll
                for (int mi = 0; mi < 2; mi++) {
                    hmma(acc[mi][2 * p + 0], af[mi], bf[p][0], bf[p][1]);
                    hmma(acc[mi][2 * p + 1], af[mi], bf[p][2], bf[p][3]);
                }
        }
    }

    // Epilogue: per-warp (32-row) max per column, staged via smem, coalesced store.
    float* sred2 = (float*)(sm + SMEM_RED);     // [128 b][4 wm]
    __syncthreads();                             // smem stages no longer needed
    #pragma unroll
    for (int ni = 0; ni < 8; ni++) {
        #pragma unroll
        for (int c2 = 0; c2 < 2; c2++) {
            float v = fmaxf(fmaxf(acc[0][ni][c2], acc[0][ni][c2 + 2]),
                            fmaxf(acc[1][ni][c2], acc[1][ni][c2 + 2]));
            v = fmaxf(v, __shfl_xor_sync(0xffffffffu, v, 4));
            v = fmaxf(v, __shfl_xor_sync(0xffffffffu, v, 8));
            v = fmaxf(v, __shfl_xor_sync(0xffffffffu, v, 16));
            if (lane < 4)
                sred2[(wn * 64 + ni * 8 + lane * 2 + c2) * 4 + wm] = v;
        }
    }
    __syncthreads();
    if (tid < BN) {
        float4 v4 = ((const float4*)sred2)[tid];
        *(float4*)(g_submax + (size_t)(b0 + tid) * NSUB + mblk * 4) = v4;
    }
}

// ---------------- phase 2: per-b global max + candidate emission ----------------
__global__ void select_kernel() {
    const int wid = threadIdx.x >> 5;
    const int lane = threadIdx.x & 31;
    const int b = blockIdx.x * 8 + wid;
    const float* row = g_submax + (size_t)b * NSUB;
    float gmax = -1e38f;
    #pragma unroll
    for (int i = 0; i < NSUB / 32; i++) gmax = fmaxf(gmax, row[lane + 32 * i]);
    #pragma unroll
    for (int o = 16; o; o >>= 1) gmax = fmaxf(gmax, __shfl_xor_sync(0xffffffffu, gmax, o));
    const float thr = gmax - MARGIN;
    #pragma unroll
    for (int i = 0; i < NSUB / 32; i++) {
        int sub = lane + 32 * i;
        if (row[sub] >= thr) {
            int p = atomicAdd(&g_ncand, 1);
            g_cand[p] = (b << 16) | sub;
        }
    }
}

// ---------------- phase 3: exact fp32 rescore of 32-row candidate sub-blocks ----------------
__global__ __launch_bounds__(256) void rescore_kernel(const float* __restrict__ mem) {
    __shared__ float ctx_s[D];
    const int tid = threadIdx.x;
    const int wid = tid >> 5;
    const int lane = tid & 31;
    const int ncand = g_ncand;

    for (int c = blockIdx.x; c < ncand; c += gridDim.x) {
        const int e = g_cand[c];
        const int b = e >> 16;
        const int m0 = (e & 0xffff) * 32;
        ctx_s[tid] = g_ctxn[(size_t)b * D + tid];
        ctx_s[tid + 256] = g_ctxn[(size_t)b * D + tid + 256];
        __syncthreads();
        const float4* ctx4 = (const float4*)ctx_s;

        unsigned long long wbest = 0ULL;
        #pragma unroll
        for (int r = 0; r < 4; r++) {
            const int row = m0 + wid * 4 + r;
            const float4* mrow = (const float4*)(mem + (size_t)row * D);
            float s = 0.f;
            #pragma unroll
            for (int j = 0; j < 4; j++) {
                float4 mv = mrow[lane + 32 * j];
                float4 cv = ctx4[lane + 32 * j];
                s += mv.x * cv.x + mv.y * cv.y + mv.z * cv.z + mv.w * cv.w;
            }
            #pragma unroll
            for (int o = 16; o; o >>= 1) s += __shfl_xor_sync(0xffffffffu, s, o);
            float sc = s * g_minv[row];
            unsigned u = __float_as_uint(sc);
            u = (u & 0x80000000u) ? ~u : (u | 0x80000000u);
            unsigned long long key = ((unsigned long long)u << 32) | (unsigned)(~row);
            if (key > wbest) wbest = key;
        }
        if (lane == 0) atomicMax(&g_best[b], wbest);
        __syncthreads();
    }
}

// ---------------- gather winning rows ----------------
__global__ void gather_kernel(const float* __restrict__ mem, float* __restrict__ out) {
    const int b = blockIdx.x;
    const int t = threadIdx.x;   // 128
    unsigned idx = ~(unsigned)(g_best[b] & 0xffffffffull);
    ((float4*)(out + (size_t)b * D))[t] = ((const float4*)(mem + (size_t)idx * D))[t];
}

// ---------------- launch ----------------
extern "C" void kernel_launch(void* const* d_in, const int* in_sizes, int n_in,
                              void* d_out, int out_size) {
    const float* ctx = (const float*)d_in[0];
    const float* mem = (const float*)d_in[1];
    if (n_in >= 2 && in_sizes[0] > in_sizes[1]) {
        const float* t = ctx; ctx = mem; mem = t;
    }
    float* out = (float*)d_out;

    cudaFuncSetAttribute(score_gemm_kernel,
                         cudaFuncAttributeMaxDynamicSharedMemorySize, SMEM_TOT);

    ctx_prep_kernel<<<NB, 128>>>(ctx);
    mem_prep_kernel<<<NM / 8, 256>>>(mem);
    dim3 grid(NB / BN, NM / BM);   // (4, 512): b fastest -> mem tiles shared in L2
    score_gemm_kernel<<<grid, 256, SMEM_TOT>>>();
    select_kernel<<<NB / 8, 256>>>();
    rescore_kernel<<<512, 256>>>(mem);
    gather_kernel<<<NB, 128>>>(mem, out);
}

// round 6
// speedup vs baseline: 4.3487x; 1.0043x over previous
#include <cuda_runtime.h>
#include <cuda_bf16.h>
#include <cstdint>

#define D      512
#define NB     512       // context rows (B)
#define NM     65536     // memory rows (M)
#define BM     128       // m rows per CTA tile
#define BN     128       // b cols per CTA tile
#define BK     32        // k per pipeline stage
#define NSUB   (NM / 32) // 2048 sub-blocks of 32 rows
#define NKS    (D / BK)  // 16 k stages
#define NSTAGE 4
#define LDA    40        // padded smem row stride (elems) -> conflict-free ldmatrix
#define STAGE_E (BM * LDA)            // elems per operand per stage (5120)
#define STAGE_B (STAGE_E * 2)         // bytes (10240)
#define MARGIN 0.0078125f             // 2^-7 >= 2x worst-case bf16 dot error

// ---------------- device scratch (no cudaMalloc allowed) ----------------
__device__ float          g_ctxn[NB * D];          // normalized ctx fp32 (exact rescore)
__device__ __nv_bfloat16  g_ctxb[NB * D];          // normalized ctx bf16
__device__ __nv_bfloat16  g_memb[(size_t)NM * D];  // normalized mem bf16 (64MB)
__device__ float          g_minv[NM];
__device__ float          g_submax[(size_t)NB * NSUB];  // [b][sub] 4MB

// ---------------- ctx: normalize -> fp32 + bf16 ----------------
__global__ void ctx_prep_kernel(const float* __restrict__ ctx) {
    const int b = blockIdx.x;
    const int t = threadIdx.x;                     // 128 threads, one float4 each
    float4 v = ((const float4*)(ctx + (size_t)b * D))[t];
    float ss = v.x * v.x + v.y * v.y + v.z * v.z + v.w * v.w;
    #pragma unroll
    for (int o = 16; o; o >>= 1) ss += __shfl_xor_sync(0xffffffffu, ss, o);
    __shared__ float ws[4];
    if ((t & 31) == 0) ws[t >> 5] = ss;
    __syncthreads();
    float sc = rsqrtf(fmaxf(ws[0] + ws[1] + ws[2] + ws[3], 1e-12f));
    float4 n4 = make_float4(v.x * sc, v.y * sc, v.z * sc, v.w * sc);
    ((float4*)(g_ctxn + (size_t)b * D))[t] = n4;
    __nv_bfloat162 p0 = __floats2bfloat162_rn(n4.x, n4.y);
    __nv_bfloat162 p1 = __floats2bfloat162_rn(n4.z, n4.w);
    uint2 u = make_uint2(*(uint32_t*)&p0, *(uint32_t*)&p1);
    *(uint2*)(g_ctxb + (size_t)b * D + 4 * t) = u;
}

// ---------------- mem: inv-norm + normalized bf16 ----------------
__global__ void mem_prep_kernel(const float* __restrict__ mem) {
    const int warp = threadIdx.x >> 5;
    const int lane = threadIdx.x & 31;
    const int m = blockIdx.x * 8 + warp;
    const float4* row = (const float4*)(mem + (size_t)m * D);
    float4 v[4];
    float ss = 0.f;
    #pragma unroll
    for (int i = 0; i < 4; i++) {
        v[i] = row[lane + 32 * i];
        ss += v[i].x * v[i].x + v[i].y * v[i].y + v[i].z * v[i].z + v[i].w * v[i].w;
    }
    #pragma unroll
    for (int o = 16; o; o >>= 1) ss += __shfl_xor_sync(0xffffffffu, ss, o);
    float inv = rsqrtf(fmaxf(ss, 1e-12f));
    if (lane == 0) g_minv[m] = inv;
    #pragma unroll
    for (int i = 0; i < 4; i++) {
        __nv_bfloat162 p0 = __floats2bfloat162_rn(v[i].x * inv, v[i].y * inv);
        __nv_bfloat162 p1 = __floats2bfloat162_rn(v[i].z * inv, v[i].w * inv);
        uint2 u = make_uint2(*(uint32_t*)&p0, *(uint32_t*)&p1);
        *(uint2*)(g_memb + (size_t)m * D + 4 * (lane + 32 * i)) = u;
    }
}

// ---------------- asm helpers ----------------
__device__ __forceinline__ uint32_t smem_u32(const void* p) {
    uint32_t a;
    asm("{ .reg .u64 t; cvta.to.shared.u64 t, %1; cvt.u32.u64 %0, t; }" : "=r"(a) : "l"(p));
    return a;
}
__device__ __forceinline__ void cpa16(uint32_t dst, const void* src) {
    asm volatile("cp.async.cg.shared.global [%0], [%1], 16;" :: "r"(dst), "l"(src));
}
__device__ __forceinline__ void cpa_commit() {
    asm volatile("cp.async.commit_group;");
}
__device__ __forceinline__ void cpa_wait2() {
    asm volatile("cp.async.wait_group 2;");
}
__device__ __forceinline__ void ldsm_x4(uint32_t& r0, uint32_t& r1, uint32_t& r2, uint32_t& r3,
                                        uint32_t addr) {
    asm volatile("ldmatrix.sync.aligned.m8n8.x4.shared.b16 {%0,%1,%2,%3}, [%4];"
                 : "=r"(r0), "=r"(r1), "=r"(r2), "=r"(r3) : "r"(addr));
}
__device__ __forceinline__ void hmma(float* c, const uint32_t* a, uint32_t b0, uint32_t b1) {
    asm volatile(
        "mma.sync.aligned.m16n8k16.row.col.f32.bf16.bf16.f32 "
        "{%0,%1,%2,%3}, {%4,%5,%6,%7}, {%8,%9}, {%0,%1,%2,%3};"
        : "+f"(c[0]), "+f"(c[1]), "+f"(c[2]), "+f"(c[3])
        : "r"(a[0]), "r"(a[1]), "r"(a[2]), "r"(a[3]), "r"(b0), "r"(b1));
}

// ---------------- phase 1: bf16 GEMM + per-(b, 32-row-sub) max ----------------
// CTA: 128 m x 128 b, 256 threads (8 warps: 4 m-warps (wm) x 2 n-warps (wn)).
// Warp tile 32(m) x 64(n): 2 m-frags x 8 n-frags of m16n8k16.
#define SMEM_RED (NSTAGE * 2 * STAGE_B)        // 81920: after 4 stages of A+B
#define SMEM_TOT (SMEM_RED + BN * 4 * 4)       // + sred2[128][4] floats

__global__ __launch_bounds__(256, 2) void score_gemm_kernel() {
    extern __shared__ char sm[];
    const uint32_t smb = smem_u32(sm);
    const int tid  = threadIdx.x;
    const int lane = tid & 31;
    const int wid  = tid >> 5;
    const int wm   = wid & 3;
    const int wn   = wid >> 2;
    const int b0   = blockIdx.x * BN;
    const int mblk = blockIdx.y;
    const int m0   = mblk * BM;

    // per-thread load slots: 2 A chunks + 2 B chunks of 16B
    const int r0c = tid >> 2, c0c = tid & 3;
    const int r1c = (tid + 256) >> 2, c1c = (tid + 256) & 3;

    auto load_stage = [&](int ks) {
        const int st = ks & (NSTAGE - 1);
        const uint32_t aB = smb + st * (2 * STAGE_B);
        const uint32_t bB = aB + STAGE_B;
        const __nv_bfloat16* gA = g_memb + (size_t)m0 * D + ks * BK;
        const __nv_bfloat16* gB = g_ctxb + (size_t)b0 * D + ks * BK;
        cpa16(aB + (r0c * LDA + c0c * 8) * 2, gA + (size_t)r0c * D + c0c * 8);
        cpa16(aB + (r1c * LDA + c1c * 8) * 2, gA + (size_t)r1c * D + c1c * 8);
        cpa16(bB + (r0c * LDA + c0c * 8) * 2, gB + (size_t)r0c * D + c0c * 8);
        cpa16(bB + (r1c * LDA + c1c * 8) * 2, gB + (size_t)r1c * D + c1c * 8);
    };

    load_stage(0); cpa_commit();
    load_stage(1); cpa_commit();
    load_stage(2); cpa_commit();

    float acc[2][8][4];
    #pragma unroll
    for (int mi = 0; mi < 2; mi++)
        #pragma unroll
        for (int ni = 0; ni < 8; ni++)
            #pragma unroll
            for (int q = 0; q < 4; q++) acc[mi][ni][q] = 0.f;

    // ldmatrix lane address components
    const int a_row = (lane & 7) + ((lane >> 3) & 1) * 8;
    const int a_col = (lane >> 4) * 8;
    const int b_row = (lane & 7) + ((lane >> 4) << 3);
    const int b_col = ((lane >> 3) & 1) * 8;

    for (int ks = 0; ks < NKS; ks++) {
        cpa_wait2();                   // stage ks resident
        __syncthreads();               // visible to all; stage (ks+3)&3 free
        if (ks + 3 < NKS) load_stage(ks + 3);
        cpa_commit();                  // unconditional: keeps group count aligned

        const int st = ks & (NSTAGE - 1);
        const uint32_t aB = smb + st * (2 * STAGE_B);
        const uint32_t bB = aB + STAGE_B;
        #pragma unroll
        for (int kh = 0; kh < 2; kh++) {
            // batch all 6 ldmatrix first, then 16 HMMA (latency overlap)
            uint32_t af[2][4];
            uint32_t bf[4][4];
            #pragma unroll
            for (int mi = 0; mi < 2; mi++) {
                uint32_t addr = aB + ((wm * 32 + mi * 16 + a_row) * LDA + kh * 16 + a_col) * 2;
                ldsm_x4(af[mi][0], af[mi][1], af[mi][2], af[mi][3], addr);
            }
            #pragma unroll
            for (int p = 0; p < 4; p++) {
                uint32_t addr = bB + ((wn * 64 + p * 16 + b_row) * LDA + kh * 16 + b_col) * 2;
                ldsm_x4(bf[p][0], bf[p][1], bf[p][2], bf[p][3], addr);
            }
            #pragma unroll
            for (int p = 0; p < 4; p++)
                #pragma unroll
                for (int mi = 0; mi < 2; mi++) {
                    hmma(acc[mi][2 * p + 0], af[mi], bf[p][0], bf[p][1]);
                    hmma(acc[mi][2 * p + 1], af[mi], bf[p][2], bf[p][3]);
                }
        }
    }

    // Epilogue: per-warp (32-row) max per column, staged via smem, coalesced store.
    float* sred2 = (float*)(sm + SMEM_RED);     // [128 b][4 wm]
    __syncthreads();                             // smem stages no longer needed
    #pragma unroll
    for (int ni = 0; ni < 8; ni++) {
        #pragma unroll
        for (int c2 = 0; c2 < 2; c2++) {
            float v = fmaxf(fmaxf(acc[0][ni][c2], acc[0][ni][c2 + 2]),
                            fmaxf(acc[1][ni][c2], acc[1][ni][c2 + 2]));
            v = fmaxf(v, __shfl_xor_sync(0xffffffffu, v, 4));
            v = fmaxf(v, __shfl_xor_sync(0xffffffffu, v, 8));
            v = fmaxf(v, __shfl_xor_sync(0xffffffffu, v, 16));
            if (lane < 4)
                sred2[(wn * 64 + ni * 8 + lane * 2 + c2) * 4 + wm] = v;
        }
    }
    __syncthreads();
    if (tid < BN) {
        float4 v4 = ((const float4*)sred2)[tid];
        *(float4*)(g_submax + (size_t)(b0 + tid) * NSUB + mblk * 4) = v4;
    }
}

// ---------------- phase 2 (fused): select + exact rescore + gather, one CTA per b ----------------
__global__ __launch_bounds__(256) void finalize_kernel(const float* __restrict__ mem,
                                                       float* __restrict__ out) {
    const int b = blockIdx.x;
    const int tid = threadIdx.x;
    const int wid = tid >> 5;
    const int lane = tid & 31;

    __shared__ float ctx_s[D];
    __shared__ float sred[8];
    __shared__ unsigned long long wkey[8];
    __shared__ int clist[256];
    __shared__ int scnt;
    __shared__ unsigned s_idx;

    // stage ctx (fp32, normalized) while scanning submax
    ctx_s[tid]       = g_ctxn[(size_t)b * D + tid];
    ctx_s[tid + 256] = g_ctxn[(size_t)b * D + tid + 256];
    if (tid == 0) scnt = 0;

    // 1) per-b global max over 2048 sub-block maxima (8 per thread, in regs)
    const float* row = g_submax + (size_t)b * NSUB;
    float vals[8];
    float lmax = -1e38f;
    #pragma unroll
    for (int i = 0; i < 8; i++) {
        vals[i] = row[tid + 256 * i];
        lmax = fmaxf(lmax, vals[i]);
    }
    #pragma unroll
    for (int o = 16; o; o >>= 1) lmax = fmaxf(lmax, __shfl_xor_sync(0xffffffffu, lmax, o));
    if (lane == 0) sred[wid] = lmax;
    __syncthreads();
    float gmax = sred[0];
    #pragma unroll
    for (int w = 1; w < 8; w++) gmax = fmaxf(gmax, sred[w]);
    const float thr = gmax - MARGIN;

    // 2) candidate sub-blocks (typically 1-2)
    #pragma unroll
    for (int i = 0; i < 8; i++) {
        if (vals[i] >= thr) {
            int p = atomicAdd(&scnt, 1);
            if (p < 256) clist[p] = tid + 256 * i;
        }
    }
    __syncthreads();
    const int cnt = (scnt < 256) ? scnt : 256;
    const float4* ctx4 = (const float4*)ctx_s;

    // 3) exact fp32 rescore: 8 warps x 4 rows per 32-row sub-block
    unsigned long long best = 0ULL;
    for (int ci = 0; ci < cnt; ci++) {
        const int m0 = clist[ci] * 32;
        #pragma unroll
        for (int r = 0; r < 4; r++) {
            const int mrowi = m0 + wid * 4 + r;
            const float4* mrow = (const float4*)(mem + (size_t)mrowi * D);
            float s = 0.f;
            #pragma unroll
            for (int j = 0; j < 4; j++) {
                float4 mv = mrow[lane + 32 * j];
                float4 cv = ctx4[lane + 32 * j];
                s += mv.x * cv.x + mv.y * cv.y + mv.z * cv.z + mv.w * cv.w;
            }
            #pragma unroll
            for (int o = 16; o; o >>= 1) s += __shfl_xor_sync(0xffffffffu, s, o);
            float sc = s * g_minv[mrowi];
            unsigned u = __float_as_uint(sc);
            u = (u & 0x80000000u) ? ~u : (u | 0x80000000u);   // order-preserving key
            unsigned long long key = ((unsigned long long)u << 32) | (unsigned)(~mrowi);
            if (key > best) best = key;                        // smallest row wins ties
        }
    }
    if (lane == 0) wkey[wid] = best;
    __syncthreads();
    if (tid == 0) {
        unsigned long long bb = wkey[0];
        #pragma unroll
        for (int w = 1; w < 8; w++) if (wkey[w] > bb) bb = wkey[w];
        s_idx = ~(unsigned)(bb & 0xffffffffull);
    }
    __syncthreads();

    // 4) gather winning row to output
    if (tid < 128) {
        const unsigned idx = s_idx;
        ((float4*)(out + (size_t)b * D))[tid] =
            ((const float4*)(mem + (size_t)idx * D))[tid];
    }
}

// ---------------- launch ----------------
extern "C" void kernel_launch(void* const* d_in, const int* in_sizes, int n_in,
                              void* d_out, int out_size) {
    const float* ctx = (const float*)d_in[0];
    const float* mem = (const float*)d_in[1];
    if (n_in >= 2 && in_sizes[0] > in_sizes[1]) {
        const float* t = ctx; ctx = mem; mem = t;
    }
    float* out = (float*)d_out;

    cudaFuncSetAttribute(score_gemm_kernel,
                         cudaFuncAttributeMaxDynamicSharedMemorySize, SMEM_TOT);

    ctx_prep_kernel<<<NB, 128>>>(ctx);
    mem_prep_kernel<<<NM / 8, 256>>>(mem);
    dim3 grid(NB / BN, NM / BM);   // (4, 512): b fastest -> mem tiles shared in L2
    score_gemm_kernel<<<grid, 256, SMEM_TOT>>>();
    finalize_kernel<<<NB, 256>>>(mem, out);
}

// round 8
// speedup vs baseline: 5.0496x; 1.1612x over previous
#include <cuda_runtime.h>
#include <cuda_fp16.h>
#include <cstdint>

#define D      512
#define NB     512       // context rows (B)
#define NM     65536     // memory rows (M)
#define BM     128       // m rows per CTA tile
#define BN     128       // b cols per CTA tile
#define BK     32        // k per pipeline stage
#define NSUB   (NM / 32) // 2048 sub-blocks of 32 rows
#define NKS    (D / BK)  // 16 k stages
#define NSTAGE 5
#define LDA    40        // padded smem row stride (elems) -> conflict-free ldmatrix
#define STAGE_E (BM * LDA)            // elems per operand per stage (5120)
#define STAGE_B (STAGE_E * 2)         // bytes (10240)
#define MARGIN 0.0025f   // > 2x (fp16 dot err 2^-10 + fp32 accum err ~3e-5)

// ---------------- device scratch (no cudaMalloc allowed) ----------------
__device__ float   g_ctxn[NB * D];           // normalized ctx fp32 (exact rescore)
__device__ __half  g_ctxh[NB * D];           // normalized ctx fp16
__device__ __half  g_memh[(size_t)NM * D];   // normalized mem fp16 (64MB)
__device__ float   g_minv[NM];
__device__ float   g_submax[(size_t)NB * NSUB];  // [b][sub] 4MB

// ---------------- ctx: normalize -> fp32 + fp16 ----------------
__global__ void ctx_prep_kernel(const float* __restrict__ ctx) {
    const int b = blockIdx.x;
    const int t = threadIdx.x;                     // 128 threads, one float4 each
    float4 v = ((const float4*)(ctx + (size_t)b * D))[t];
    float ss = v.x * v.x + v.y * v.y + v.z * v.z + v.w * v.w;
    #pragma unroll
    for (int o = 16; o; o >>= 1) ss += __shfl_xor_sync(0xffffffffu, ss, o);
    __shared__ float ws[4];
    if ((t & 31) == 0) ws[t >> 5] = ss;
    __syncthreads();
    float sc = rsqrtf(fmaxf(ws[0] + ws[1] + ws[2] + ws[3], 1e-12f));
    float4 n4 = make_float4(v.x * sc, v.y * sc, v.z * sc, v.w * sc);
    ((float4*)(g_ctxn + (size_t)b * D))[t] = n4;
    __half2 p0 = __floats2half2_rn(n4.x, n4.y);
    __half2 p1 = __floats2half2_rn(n4.z, n4.w);
    uint2 u = make_uint2(*(uint32_t*)&p0, *(uint32_t*)&p1);
    *(uint2*)(g_ctxh + (size_t)b * D + 4 * t) = u;
}

// ---------------- mem: inv-norm + normalized fp16 ----------------
__global__ void mem_prep_kernel(const float* __restrict__ mem) {
    const int warp = threadIdx.x >> 5;
    const int lane = threadIdx.x & 31;
    const int m = blockIdx.x * 8 + warp;
    const float4* row = (const float4*)(mem + (size_t)m * D);
    float4 v[4];
    float ss = 0.f;
    #pragma unroll
    for (int i = 0; i < 4; i++) {
        v[i] = row[lane + 32 * i];
        ss += v[i].x * v[i].x + v[i].y * v[i].y + v[i].z * v[i].z + v[i].w * v[i].w;
    }
    #pragma unroll
    for (int o = 16; o; o >>= 1) ss += __shfl_xor_sync(0xffffffffu, ss, o);
    float inv = rsqrtf(fmaxf(ss, 1e-12f));
    if (lane == 0) g_minv[m] = inv;
    #pragma unroll
    for (int i = 0; i < 4; i++) {
        __half2 p0 = __floats2half2_rn(v[i].x * inv, v[i].y * inv);
        __half2 p1 = __floats2half2_rn(v[i].z * inv, v[i].w * inv);
        uint2 u = make_uint2(*(uint32_t*)&p0, *(uint32_t*)&p1);
        *(uint2*)(g_memh + (size_t)m * D + 4 * (lane + 32 * i)) = u;
    }
}

// ---------------- asm helpers ----------------
__device__ __forceinline__ uint32_t smem_u32(const void* p) {
    uint32_t a;
    asm("{ .reg .u64 t; cvta.to.shared.u64 t, %1; cvt.u32.u64 %0, t; }" : "=r"(a) : "l"(p));
    return a;
}
__device__ __forceinline__ void cpa16(uint32_t dst, const void* src) {
    asm volatile("cp.async.cg.shared.global [%0], [%1], 16;" :: "r"(dst), "l"(src));
}
__device__ __forceinline__ void cpa_commit() {
    asm volatile("cp.async.commit_group;");
}
__device__ __forceinline__ void cpa_wait3() {
    asm volatile("cp.async.wait_group 3;");
}
__device__ __forceinline__ void ldsm_x4(uint32_t& r0, uint32_t& r1, uint32_t& r2, uint32_t& r3,
                                        uint32_t addr) {
    asm volatile("ldmatrix.sync.aligned.m8n8.x4.shared.b16 {%0,%1,%2,%3}, [%4];"
                 : "=r"(r0), "=r"(r1), "=r"(r2), "=r"(r3) : "r"(addr));
}
__device__ __forceinline__ void hmma(float* c, const uint32_t* a, uint32_t b0, uint32_t b1) {
    asm volatile(
        "mma.sync.aligned.m16n8k16.row.col.f32.f16.f16.f32 "
        "{%0,%1,%2,%3}, {%4,%5,%6,%7}, {%8,%9}, {%0,%1,%2,%3};"
        : "+f"(c[0]), "+f"(c[1]), "+f"(c[2]), "+f"(c[3])
        : "r"(a[0]), "r"(a[1]), "r"(a[2]), "r"(a[3]), "r"(b0), "r"(b1));
}

// ---------------- phase 1: fp16 GEMM + per-(b, 32-row-sub) max ----------------
// CTA: 128 m x 128 b, 256 threads (8 warps: 4 m-warps (wm) x 2 n-warps (wn)).
// Warp tile 32(m) x 64(n): 2 m-frags x 8 n-frags of m16n8k16.
#define SMEM_RED (NSTAGE * 2 * STAGE_B)        // 102400: after 5 stages of A+B
#define SMEM_TOT (SMEM_RED + BN * 4 * 4)       // + sred2[128][4] floats

__global__ __launch_bounds__(256, 2) void score_gemm_kernel() {
    extern __shared__ char sm[];
    const uint32_t smb = smem_u32(sm);
    const int tid  = threadIdx.x;
    const int lane = tid & 31;
    const int wid  = tid >> 5;
    const int wm   = wid & 3;
    const int wn   = wid >> 2;
    const int b0   = blockIdx.x * BN;
    const int mblk = blockIdx.y;
    const int m0   = mblk * BM;

    // per-thread load slots: 2 A chunks + 2 B chunks of 16B
    const int r0c = tid >> 2, c0c = tid & 3;
    const int r1c = (tid + 256) >> 2, c1c = (tid + 256) & 3;

    auto load_stage = [&](int ks) {
        const int st = ks % NSTAGE;
        const uint32_t aB = smb + st * (2 * STAGE_B);
        const uint32_t bB = aB + STAGE_B;
        const __half* gA = g_memh + (size_t)m0 * D + ks * BK;
        const __half* gB = g_ctxh + (size_t)b0 * D + ks * BK;
        cpa16(aB + (r0c * LDA + c0c * 8) * 2, gA + (size_t)r0c * D + c0c * 8);
        cpa16(aB + (r1c * LDA + c1c * 8) * 2, gA + (size_t)r1c * D + c1c * 8);
        cpa16(bB + (r0c * LDA + c0c * 8) * 2, gB + (size_t)r0c * D + c0c * 8);
        cpa16(bB + (r1c * LDA + c1c * 8) * 2, gB + (size_t)r1c * D + c1c * 8);
    };

    load_stage(0); cpa_commit();
    load_stage(1); cpa_commit();
    load_stage(2); cpa_commit();
    load_stage(3); cpa_commit();

    float acc[2][8][4];
    #pragma unroll
    for (int mi = 0; mi < 2; mi++)
        #pragma unroll
        for (int ni = 0; ni < 8; ni++)
            #pragma unroll
            for (int q = 0; q < 4; q++) acc[mi][ni][q] = 0.f;

    // ldmatrix lane address components
    const int a_row = (lane & 7) + ((lane >> 3) & 1) * 8;
    const int a_col = (lane >> 4) * 8;
    const int b_row = (lane & 7) + ((lane >> 4) << 3);
    const int b_col = ((lane >> 3) & 1) * 8;

    for (int ks = 0; ks < NKS; ks++) {
        cpa_wait3();                   // stage ks (and ks+1) resident
        __syncthreads();               // all warps past iter ks-1: stage (ks+4)%5 free
        if (ks + 4 < NKS) load_stage(ks + 4);
        cpa_commit();                  // unconditional: keeps group count aligned

        const int st = ks % NSTAGE;
        const uint32_t aB = smb + st * (2 * STAGE_B);
        const uint32_t bB = aB + STAGE_B;
        #pragma unroll
        for (int kh = 0; kh < 2; kh++) {
            // batch all 6 ldmatrix first, then 16 HMMA (latency overlap)
            uint32_t af[2][4];
            uint32_t bf[4][4];
            #pragma unroll
            for (int mi = 0; mi < 2; mi++) {
                uint32_t addr = aB + ((wm * 32 + mi * 16 + a_row) * LDA + kh * 16 + a_col) * 2;
                ldsm_x4(af[mi][0], af[mi][1], af[mi][2], af[mi][3], addr);
            }
            #pragma unroll
            for (int p = 0; p < 4; p++) {
                uint32_t addr = bB + ((wn * 64 + p * 16 + b_row) * LDA + kh * 16 + b_col) * 2;
                ldsm_x4(bf[p][0], bf[p][1], bf[p][2], bf[p][3], addr);
            }
            #pragma unroll
            for (int p = 0; p < 4; p++)
                #pragma unroll
                for (int mi = 0; mi < 2; mi++) {
                    hmma(acc[mi][2 * p + 0], af[mi], bf[p][0], bf[p][1]);
                    hmma(acc[mi][2 * p + 1], af[mi], bf[p][2], bf[p][3]);
                }
        }
    }

    // Epilogue: per-warp (32-row) max per column, staged via smem, coalesced store.
    float* sred2 = (float*)(sm + SMEM_RED);     // [128 b][4 wm]
    __syncthreads();                             // smem stages no longer needed
    #pragma unroll
    for (int ni = 0; ni < 8; ni++) {
        #pragma unroll
        for (int c2 = 0; c2 < 2; c2++) {
            float v = fmaxf(fmaxf(acc[0][ni][c2], acc[0][ni][c2 + 2]),
                            fmaxf(acc[1][ni][c2], acc[1][ni][c2 + 2]));
            v = fmaxf(v, __shfl_xor_sync(0xffffffffu, v, 4));
            v = fmaxf(v, __shfl_xor_sync(0xffffffffu, v, 8));
            v = fmaxf(v, __shfl_xor_sync(0xffffffffu, v, 16));
            if (lane < 4)
                sred2[(wn * 64 + ni * 8 + lane * 2 + c2) * 4 + wm] = v;
        }
    }
    __syncthreads();
    if (tid < BN) {
        float4 v4 = ((const float4*)sred2)[tid];
        *(float4*)(g_submax + (size_t)(b0 + tid) * NSUB + mblk * 4) = v4;
    }
}

// ---------------- phase 2 (fused): select + exact rescore + gather, one CTA per b ----------------
__global__ __launch_bounds__(256) void finalize_kernel(const float* __restrict__ mem,
                                                       float* __restrict__ out) {
    const int b = blockIdx.x;
    const int tid = threadIdx.x;
    const int wid = tid >> 5;
    const int lane = tid & 31;

    __shared__ float ctx_s[D];
    __shared__ float sred[8];
    __shared__ unsigned long long wkey[8];
    __shared__ int clist[256];
    __shared__ int scnt;
    __shared__ unsigned s_idx;

    // stage ctx (fp32, normalized) while scanning submax
    ctx_s[tid]       = g_ctxn[(size_t)b * D + tid];
    ctx_s[tid + 256] = g_ctxn[(size_t)b * D + tid + 256];
    if (tid == 0) scnt = 0;

    // 1) per-b global max over 2048 sub-block maxima (8 per thread, in regs)
    const float* row = g_submax + (size_t)b * NSUB;
    float vals[8];
    float lmax = -1e38f;
    #pragma unroll
    for (int i = 0; i < 8; i++) {
        vals[i] = row[tid + 256 * i];
        lmax = fmaxf(lmax, vals[i]);
    }
    #pragma unroll
    for (int o = 16; o; o >>= 1) lmax = fmaxf(lmax, __shfl_xor_sync(0xffffffffu, lmax, o));
    if (lane == 0) sred[wid] = lmax;
    __syncthreads();
    float gmax = sred[0];
    #pragma unroll
    for (int w = 1; w < 8; w++) gmax = fmaxf(gmax, sred[w]);
    const float thr = gmax - MARGIN;

    // 2) candidate sub-blocks (typically 1-2)
    #pragma unroll
    for (int i = 0; i < 8; i++) {
        if (vals[i] >= thr) {
            int p = atomicAdd(&scnt, 1);
            if (p < 256) clist[p] = tid + 256 * i;
        }
    }
    __syncthreads();
    const int cnt = (scnt < 256) ? scnt : 256;
    const float4* ctx4 = (const float4*)ctx_s;

    // 3) exact fp32 rescore: 8 warps x 4 rows per 32-row sub-block
    unsigned long long best = 0ULL;
    for (int ci = 0; ci < cnt; ci++) {
        const int m0 = clist[ci] * 32;
        #pragma unroll
        for (int r = 0; r < 4; r++) {
            const int mrowi = m0 + wid * 4 + r;
            const float4* mrow = (const float4*)(mem + (size_t)mrowi * D);
            float s = 0.f;
            #pragma unroll
            for (int j = 0; j < 4; j++) {
                float4 mv = mrow[lane + 32 * j];
                float4 cv = ctx4[lane + 32 * j];
                s += mv.x * cv.x + mv.y * cv.y + mv.z * cv.z + mv.w * cv.w;
            }
            #pragma unroll
            for (int o = 16; o; o >>= 1) s += __shfl_xor_sync(0xffffffffu, s, o);
            float sc = s * g_minv[mrowi];
            unsigned u = __float_as_uint(sc);
            u = (u & 0x80000000u) ? ~u : (u | 0x80000000u);   // order-preserving key
            unsigned long long key = ((unsigned long long)u << 32) | (unsigned)(~mrowi);
            if (key > best) best = key;                        // smallest row wins ties
        }
    }
    if (lane == 0) wkey[wid] = best;
    __syncthreads();
    if (tid == 0) {
        unsigned long long bb = wkey[0];
        #pragma unroll
        for (int w = 1; w < 8; w++) if (wkey[w] > bb) bb = wkey[w];
        s_idx = ~(unsigned)(bb & 0xffffffffull);
    }
    __syncthreads();

    // 4) gather winning row to output
    if (tid < 128) {
        const unsigned idx = s_idx;
        ((float4*)(out + (size_t)b * D))[tid] =
            ((const float4*)(mem + (size_t)idx * D))[tid];
    }
}

// ---------------- launch ----------------
extern "C" void kernel_launch(void* const* d_in, const int* in_sizes, int n_in,
                              void* d_out, int out_size) {
    const float* ctx = (const float*)d_in[0];
    const float* mem = (const float*)d_in[1];
    if (n_in >= 2 && in_sizes[0] > in_sizes[1]) {
        const float* t = ctx; ctx = mem; mem = t;
    }
    float* out = (float*)d_out;

    cudaFuncSetAttribute(score_gemm_kernel,
                         cudaFuncAttributeMaxDynamicSharedMemorySize, SMEM_TOT);

    ctx_prep_kernel<<<NB, 128>>>(ctx);
    mem_prep_kernel<<<NM / 8, 256>>>(mem);
    dim3 grid(NB / BN, NM / BM);   // (4, 512): b fastest -> mem tiles shared in L2
    score_gemm_kernel<<<grid, 256, SMEM_TOT>>>();
    finalize_kernel<<<NB, 256>>>(mem, out);
}